// round 14
// baseline (speedup 1.0000x reference)
#include <cuda_runtime.h>
#include <cuda_fp16.h>
#include <math.h>

#define G_TOT 2048

// ---------------- scratch (zero-initialized globals; halos never written) ----------------
__device__ __align__(128) float4 g_p0[2][G_TOT];
__device__ __align__(128) float4 g_p1[2][G_TOT];
__device__ __align__(128) float g_s0a[102*102*64];
__device__ __align__(128) float g_s0b[102*102*64];
__device__ __align__(128) float g_s0c[102*102*64];
__device__ __align__(128) float g_s0d[102*102*64];
__device__ __align__(128) float g_b1[202*202*64];
__device__ __align__(128) float g_b2[202*202*64];
__device__ __align__(128) float g_b3[202*202*64];
__device__ __align__(128) float g_b4[202*202*64];
__device__ __align__(128) unsigned g_wp[11*9*2048];   // swizzled fp16x2 weights
__device__ __align__(128) float g_part[202*512];
__device__ float g_stats[128];

#define MMA_F16(c0,c1,c2,c3,a0,a1,a2,a3,b0,b1) \
  asm("mma.sync.aligned.m16n8k16.row.col.f32.f16.f16.f32 " \
      "{%0,%1,%2,%3}, {%4,%5,%6,%7}, {%8,%9}, {%0,%1,%2,%3};" \
      : "+f"(c0),"+f"(c1),"+f"(c2),"+f"(c3) \
      : "r"(a0),"r"(a1),"r"(a2),"r"(a3),"r"(b0),"r"(b1))

// ---------------- gaussian preprocessing ----------------
__global__ void prep_k(const float* __restrict__ means, const float* __restrict__ cov,
                       const float* __restrict__ opac)
{
    int g = blockIdx.x * blockDim.x + threadIdx.x;
    if (g >= G_TOT) return;
    float mx = means[g*3+0], my = means[g*3+1], mz = means[g*3+2];
    bool pos = (mx >= -50.f) && (mx <= 50.f) && (my >= -50.f) && (my <= 50.f)
            && (mz >= -4.f)  && (mz <= 4.f);
    float c0 = cov[g*6+0], c1 = cov[g*6+1], c3 = cov[g*6+3];
    #pragma unroll
    for (int s = 0; s < 2; s++) {
        float H  = (s == 0) ? 100.f : 200.f;
        float sh = (s == 0) ? 1.f   : 2.f;
        float op = opac[g*2+s];
        bool mk = pos && (op > 0.05f);
        float u = -sh*my + 0.5f*H;
        float v = -sh*mx + 0.5f*H;
        float a  = sh*sh*c3 + 0.3f;
        float cc = sh*sh*c0 + 0.3f;
        float bb = sh*sh*c1;
        float det = fmaxf(a*cc - bb*bb, 1e-8f);
        float inv = 1.f/det;
        float ct = logf(255.f*fmaxf(op, 1e-20f));
        float rx = sqrtf(fmaxf(2.f*ct*a , 0.f));
        float ry = sqrtf(fmaxf(2.f*ct*cc, 0.f));
        if (!mk) rx = -1.f;
        g_p0[s][g] = make_float4(u, v, rx, ry);
        g_p1[s][g] = make_float4(cc*inv, -bb*inv, a*inv, op);
    }
}

__global__ void numg_k(const float* __restrict__ means, const float* __restrict__ opac,
                       float* __restrict__ out, int out_size)
{
    __shared__ int red[256];
    int tid = threadIdx.x;
    int cnt = 0;
    for (int g = tid; g < G_TOT; g += 256) {
        float mx = means[g*3], my = means[g*3+1], mz = means[g*3+2];
        bool pos = (mx >= -50.f) && (mx <= 50.f) && (my >= -50.f) && (my <= 50.f)
                && (mz >= -4.f) && (mz <= 4.f);
        if (pos) {
            if (opac[g*2+0] > 0.05f) cnt++;
            if (opac[g*2+1] > 0.05f) cnt++;
        }
    }
    red[tid] = cnt; __syncthreads();
    for (int st = 128; st > 0; st >>= 1) {
        if (tid < st) red[tid] += red[tid+st];
        __syncthreads();
    }
    if (tid == 0 && out_size > 64*200*200) out[64*200*200] = (float)red[0];
}

// ---------------- weight prep: fp16 + per-kst swizzled layout ----------------
__global__ void prep_w(const float* __restrict__ conv1w, const float* __restrict__ blkw,
                       const float* __restrict__ upw)
{
    int idx = blockIdx.x * 256 + threadIdx.x;
    if (idx >= 11*9*32*64) return;
    int co   = idx & 63;
    int pair = (idx >> 6) & 31;
    int t    = idx >> 11;
    int tap  = t % 9;
    int l    = t / 9;
    const float* src;
    if (l == 0)      src = conv1w;
    else if (l <= 4) src = blkw + (l-1)*36864;
    else if (l == 5) src = conv1w + 36864;
    else if (l == 6) src = upw;
    else             src = blkw + (l-3)*36864;
    float w0 = src[co*576 + (2*pair  )*9 + tap];
    float w1 = src[co*576 + (2*pair+1)*9 + tap];
    __half2 h = __floats2half2_rn(w0, w1);

    int kst  = pair >> 3;
    int pl_  = pair & 7;
    int qk   = pl_ & 3;
    int pgrp = pl_ >> 2;
    int qp   = co & 7;
    int n    = co >> 3;
    int slot = ((qp + 2*qk) & 7) + 8*qk;
    int dst  = (l*9 + tap)*2048 + kst*512 + (n>>2)*256 + pgrp*128 + slot*4 + (n&3);
    g_wp[dst] = *reinterpret_cast<unsigned*>(&h);
}

// ---------------- tiled ordered splatting -> padded NHWC (4 CTAs/tile, 16ch each) ------
__global__ void render_k(int s, const float* __restrict__ feats,
                         float* __restrict__ out, int H)
{
    const int W = H;
    __shared__ int s_list[G_TOT];
    __shared__ int s_wcnt[8];
    int tid = threadIdx.x;
    int lane = tid & 31, wid = tid >> 5;
    int tx0 = blockIdx.x * 16, ty0 = blockIdx.y * 16;
    int zc  = blockIdx.z;          // 0..3: channels 16*zc .. 16*zc+15
    float xmin = (float)tx0, xmax = (float)min(tx0 + 15, W - 1);
    float ymin = (float)ty0, ymax = (float)min(ty0 + 15, H - 1);

    int num = 0;
    for (int base = 0; base < G_TOT; base += 256) {
        int g = base + tid;
        float4 q = g_p0[s][g];
        bool ok = (q.z >= 0.f) &&
                  (q.x + q.z >= xmin) && (q.x - q.z <= xmax) &&
                  (q.y + q.w >= ymin) && (q.y - q.w <= ymax);
        unsigned m = __ballot_sync(0xffffffffu, ok);
        if (lane == 0) s_wcnt[wid] = __popc(m);
        __syncthreads();
        int off = num + __popc(m & ((1u << lane) - 1u));
        int tot = 0;
        #pragma unroll
        for (int w2 = 0; w2 < 8; w2++) {
            int c = s_wcnt[w2];
            if (w2 < wid) off += c;
            tot += c;
        }
        if (ok) s_list[off] = g;
        num += tot;
        __syncthreads();
    }

    int px = tx0 + (tid & 15);
    int py = ty0 + (tid >> 4);
    float fx = (float)px, fy = (float)py;
    float T = 1.f;
    float acc[16];
    #pragma unroll
    for (int d = 0; d < 16; d++) acc[d] = 0.f;

    for (int i = 0; i < num; i++) {
        int g = s_list[i];
        float4 q = g_p0[s][g];
        float4 r = g_p1[s][g];
        float dx = q.x - fx, dy = q.y - fy;
        float power = -0.5f*(r.x*dx*dx + r.z*dy*dy) - r.y*dx*dy;
        float alpha = fminf(r.w * expf(power), 0.99f);
        if (alpha >= (1.f/255.f) && power <= 0.f) {
            float wg = alpha * T;
            T *= (1.f - alpha);
            const float4* f4 = (const float4*)(feats + (size_t)g * 64 + zc * 16);
            #pragma unroll
            for (int j = 0; j < 4; j++) {
                float4 fv = __ldg(f4 + j);
                acc[4*j+0] += wg*fv.x;
                acc[4*j+1] += wg*fv.y;
                acc[4*j+2] += wg*fv.z;
                acc[4*j+3] += wg*fv.w;
            }
        }
    }
    if (px < W && py < H) {
        float4* o = (float4*)(out + (((size_t)(py+1))*(W+2) + (px+1))*64 + zc*16);
        #pragma unroll
        for (int j = 0; j < 4; j++)
            o[j] = make_float4(acc[4*j], acc[4*j+1], acc[4*j+2], acc[4*j+3]);
    }
}

// ---------------- conv3x3 64->64 via m16n8k16 fp16 (A hi/lo 2-term) ----------------
// stage_mode: 0 = read padded `in`; 1 = bilinear 2x upsample from 102-padded `in`;
//             2 = IN-fuse: (in - mu)*rstd + in2 (both 202-padded)
// add_mode:   0 none; 1 padded add; 2 unpadded add (emb); 3 IN-fuse add
__device__ __forceinline__ void epi_store(float v0, float v1, int y, int px, int ch,
    const float* add, const float* add2, int add_mode,
    float* out, int out_chw, int relu, int H, int W)
{
    if (px >= W) return;
    if (add_mode == 1) {
        float2 t = *(const float2*)(add + (((size_t)(y+1))*(W+2) + px + 1)*64 + ch);
        v0 += t.x; v1 += t.y;
    } else if (add_mode == 2) {
        float2 t = *(const float2*)(add + ((size_t)y*W + px)*64 + ch);
        v0 += t.x; v1 += t.y;
    } else if (add_mode == 3) {
        size_t o = (((size_t)(y+1))*(W+2) + px + 1)*64 + ch;
        float2 t = *(const float2*)(add + o);
        float2 a = *(const float2*)(add2 + o);
        float2 s0 = ((const float2*)g_stats)[ch];
        float2 s1 = ((const float2*)g_stats)[ch+1];
        v0 += (t.x - s0.x)*s0.y + a.x;
        v1 += (t.y - s1.x)*s1.y + a.y;
    }
    if (relu) { v0 = fmaxf(v0, 0.f); v1 = fmaxf(v1, 0.f); }
    if (out_chw) {
        out[(size_t)ch*H*W + (size_t)y*W + px]     = v0;
        out[(size_t)(ch+1)*H*W + (size_t)y*W + px] = v1;
    } else {
        *(float2*)(out + (((size_t)(y+1))*(W+2) + px + 1)*64 + ch) = make_float2(v0, v1);
    }
}

template<int NW, int ROWS, int TW, int MB>
__global__ void __launch_bounds__(NW*32, MB)
conv_mma_t(const float* __restrict__ in, const float* __restrict__ in2, int layer,
           const float* __restrict__ add, const float* __restrict__ add2,
           int stage_mode, int add_mode,
           float* __restrict__ out, int out_chw, int relu,
           int H, int W)
{
    constexpr int NT  = NW*32;
    constexpr int RS  = TW + 4;
    constexpr int AP  = (ROWS + 2) * RS;
    constexpr int APP = ((AP % 32) == 0 || (AP % 32) == 16) ? AP + 8 : AP;
    constexpr int SMA = 32 * APP;
    constexpr int WPR = NW / ROWS;
    constexpr int PXW = TW / WPR;
    constexpr int F   = PXW / 16;

    extern __shared__ unsigned smu[];
    unsigned* Ah = smu;
    unsigned* Al = smu + SMA;
    unsigned* Wb = smu + 2*SMA;

    int tid = threadIdx.x;
    int lane = tid & 31, wid = tid >> 5;
    int x0 = blockIdx.x * TW;
    int y0 = blockIdx.y * ROWS;
    int Wp = W + 2;

    for (int i = tid; i < 16*AP; i += NT) {
        int m  = i / AP;
        int rc = i - m * AP;
        int r = rc / RS;
        int c = rc - r * RS;
        int ry = y0 + r - 1;           // real coords
        int rx = x0 + c - 1;
        float4 v = make_float4(0.f, 0.f, 0.f, 0.f);
        if (stage_mode == 0) {
            if (c < TW+2 && (x0 + c) < Wp)
                v = *(const float4*)(in + (((size_t)(y0 + r))*Wp + x0 + c)*64 + m*4);
        } else if (stage_mode == 1) {
            if (c < TW+2 && ry >= 0 && ry < H && rx >= 0 && rx < W) {
                float sx = 0.5f*rx - 0.25f;
                float sy = 0.5f*ry - 0.25f;
                float fx = floorf(sx), fy = floorf(sy);
                float tx = sx - fx, ty = sy - fy;
                int xa = max((int)fx, 0), xb = min((int)fx + 1, 99);
                int ya = max((int)fy, 0), yb = min((int)fy + 1, 99);
                const float4* p00 = (const float4*)(in + (((size_t)(ya+1))*102 + xa+1)*64 + m*4);
                const float4* p01 = (const float4*)(in + (((size_t)(ya+1))*102 + xb+1)*64 + m*4);
                const float4* p10 = (const float4*)(in + (((size_t)(yb+1))*102 + xa+1)*64 + m*4);
                const float4* p11 = (const float4*)(in + (((size_t)(yb+1))*102 + xb+1)*64 + m*4);
                float4 v00 = *p00, v01 = *p01, v10 = *p10, v11 = *p11;
                float w00 = (1.f-ty)*(1.f-tx), w01 = (1.f-ty)*tx;
                float w10 = ty*(1.f-tx),       w11 = ty*tx;
                v.x = w00*v00.x + w01*v01.x + w10*v10.x + w11*v11.x;
                v.y = w00*v00.y + w01*v01.y + w10*v10.y + w11*v11.y;
                v.z = w00*v00.z + w01*v01.z + w10*v10.z + w11*v11.z;
                v.w = w00*v00.w + w01*v01.w + w10*v10.w + w11*v11.w;
            }
        } else {
            if (c < TW+2 && ry >= 0 && ry < H && rx >= 0 && rx < W) {
                size_t o = (((size_t)(y0 + r))*Wp + x0 + c)*64 + m*4;
                float4 t4 = *(const float4*)(in + o);
                float4 a4 = *(const float4*)(in2 + o);
                float2 s0 = ((const float2*)g_stats)[m*4+0];
                float2 s1 = ((const float2*)g_stats)[m*4+1];
                float2 s2 = ((const float2*)g_stats)[m*4+2];
                float2 s3 = ((const float2*)g_stats)[m*4+3];
                v.x = (t4.x - s0.x)*s0.y + a4.x;
                v.y = (t4.y - s1.x)*s1.y + a4.y;
                v.z = (t4.z - s2.x)*s2.y + a4.z;
                v.w = (t4.w - s3.x)*s3.y + a4.w;
            }
        }
        __half2 h0 = __floats2half2_rn(v.x, v.y);
        __half2 h1 = __floats2half2_rn(v.z, v.w);
        __half2 l0 = __floats2half2_rn(v.x - __low2float(h0), v.y - __high2float(h0));
        __half2 l1 = __floats2half2_rn(v.z - __low2float(h1), v.w - __high2float(h1));
        Ah[(2*m  )*APP + rc] = *reinterpret_cast<unsigned*>(&h0);
        Ah[(2*m+1)*APP + rc] = *reinterpret_cast<unsigned*>(&h1);
        Al[(2*m  )*APP + rc] = *reinterpret_cast<unsigned*>(&l0);
        Al[(2*m+1)*APP + rc] = *reinterpret_cast<unsigned*>(&l1);
    }

    int yl = wid / WPR;
    int xw = (wid % WPR) * PXW;
    int qp = lane >> 2;
    int qk = lane & 3;
    int slot4 = (((qp + 2*qk) & 7) + 8*qk) * 4;

    float acc[F][8][4];
    #pragma unroll
    for (int f = 0; f < F; f++)
        #pragma unroll
        for (int n = 0; n < 8; n++)
            #pragma unroll
            for (int j = 0; j < 4; j++) acc[f][n][j] = 0.f;

    #pragma unroll 1
    for (int tap = 0; tap < 9; tap++) {
        unsigned* Wc = Wb + (tap & 1) * 2048;
        const uint4* pw = (const uint4*)(g_wp + ((size_t)layer*9 + tap)*2048);
        for (int i = tid; i < 512; i += NT)
            *((uint4*)Wc + i) = pw[i];
        __syncthreads();

        int dy = tap / 3;
        int dx = tap - 3*dy;
        int abase = (yl + dy)*RS + xw + dx + qp;

        #pragma unroll
        for (int kst = 0; kst < 4; kst++) {
            int p0 = kst*8 + qk;
            int p1 = p0 + 4;
            unsigned ah[F][4], al[F][4];
            #pragma unroll
            for (int f = 0; f < F; f++) {
                int a0b = p0*APP + abase + f*16;
                int a1b = p1*APP + abase + f*16;
                ah[f][0] = Ah[a0b];  ah[f][1] = Ah[a0b+8];
                ah[f][2] = Ah[a1b];  ah[f][3] = Ah[a1b+8];
                al[f][0] = Al[a0b];  al[f][1] = Al[a0b+8];
                al[f][2] = Al[a1b];  al[f][3] = Al[a1b+8];
            }
            const unsigned* wk = Wc + kst*512;
            #pragma unroll
            for (int nb = 0; nb < 2; nb++) {
                uint4 H0 = *(const uint4*)(wk + nb*256 +       slot4);
                uint4 H1 = *(const uint4*)(wk + nb*256 + 128 + slot4);
                const unsigned* h0p = (const unsigned*)&H0;
                const unsigned* h1p = (const unsigned*)&H1;
                #pragma unroll
                for (int j = 0; j < 4; j++) {
                    int n = nb*4 + j;
                    unsigned w0 = h0p[j], w1 = h1p[j];
                    #pragma unroll
                    for (int f = 0; f < F; f++) {
                        MMA_F16(acc[f][n][0],acc[f][n][1],acc[f][n][2],acc[f][n][3],
                                ah[f][0],ah[f][1],ah[f][2],ah[f][3], w0,w1);
                        MMA_F16(acc[f][n][0],acc[f][n][1],acc[f][n][2],acc[f][n][3],
                                al[f][0],al[f][1],al[f][2],al[f][3], w0,w1);
                    }
                }
            }
        }
        __syncthreads();
    }

    int y = y0 + yl;
    #pragma unroll
    for (int n = 0; n < 8; n++) {
        int ch = n*8 + 2*qk;
        #pragma unroll
        for (int f = 0; f < F; f++) {
            epi_store(acc[f][n][0], acc[f][n][1], y, x0+xw+f*16+qp,   ch, add, add2, add_mode, out, out_chw, relu, H, W);
            epi_store(acc[f][n][2], acc[f][n][3], y, x0+xw+f*16+qp+8, ch, add, add2, add_mode, out, out_chw, relu, H, W);
        }
    }
}

#define SMEM100 ((2*32*152 + 2*2048)*4)
#define SMEM200 ((2*32*216 + 2*2048)*4)

// ---------------- instance norm (deterministic two-stage) ----------------
__global__ void in_rows_k(const float* __restrict__ x)   // grid 202, block 256
{
    int r = blockIdx.x;
    int c = threadIdx.x & 63;
    int q = threadIdx.x >> 6;
    const float* p = x + (size_t)r * 202 * 64;
    int pa = q * 51;
    int pb = min(pa + 51, 202);
    float s = 0.f, s2 = 0.f;
    for (int px = pa; px < pb; px++) {
        float v = p[px*64 + c];
        s += v; s2 += v*v;
    }
    g_part[(r*4 + q)*128 + c]      = s;
    g_part[(r*4 + q)*128 + 64 + c] = s2;
}

__global__ void in_stats_k()
{
    int c = threadIdx.x;
    float s = 0.f, s2 = 0.f;
    for (int r = 0; r < 808; r++) {
        s  += g_part[r*128 + c];
        s2 += g_part[r*128 + 64 + c];
    }
    float mu  = s * (1.f/40000.f);
    float var = s2 * (1.f/40000.f) - mu*mu;
    g_stats[c*2]   = mu;
    g_stats[c*2+1] = 1.f/sqrtf(var + 1e-5f);
}

// ---------------- launch ----------------
extern "C" void kernel_launch(void* const* d_in, const int* in_sizes, int n_in,
                              void* d_out, int out_size)
{
    const float* features = (const float*)d_in[0];
    const float* means    = (const float*)d_in[1];
    const float* cov      = (const float*)d_in[2];
    const float* opac     = (const float*)d_in[3];
    const float* emb      = (const float*)d_in[4];
    const float* conv1w   = (const float*)d_in[5];
    const float* blkw     = (const float*)d_in[6];
    const float* upw      = (const float*)d_in[7];
    float* out = (float*)d_out;

    cudaFuncSetAttribute(conv_mma_t<4,2,32,4>, cudaFuncAttributeMaxDynamicSharedMemorySize, SMEM100);
    cudaFuncSetAttribute(conv_mma_t<8,4,32,3>, cudaFuncAttributeMaxDynamicSharedMemorySize, SMEM200);

    float *s0a,*s0b,*s0c,*s0d,*b1,*b2,*b3,*b4;
    cudaGetSymbolAddress((void**)&s0a, g_s0a);
    cudaGetSymbolAddress((void**)&s0b, g_s0b);
    cudaGetSymbolAddress((void**)&s0c, g_s0c);
    cudaGetSymbolAddress((void**)&s0d, g_s0d);
    cudaGetSymbolAddress((void**)&b1,  g_b1);
    cudaGetSymbolAddress((void**)&b2,  g_b2);
    cudaGetSymbolAddress((void**)&b3,  g_b3);
    cudaGetSymbolAddress((void**)&b4,  g_b4);

    prep_k<<<8, 256>>>(means, cov, opac);
    numg_k<<<1, 256>>>(means, opac, out, out_size);
    prep_w<<<792, 256>>>(conv1w, blkw, upw);
    render_k<<<dim3(7,7,4),   256>>>(0, features, s0a, 100);
    render_k<<<dim3(13,13,4), 256>>>(1, features, b1, 200);

    dim3 gs0(4, 50);   // 100²: 32-px x-tiles, 2-row y-tiles -> 200 CTAs
    dim3 gs1(7, 50);   // 200²: 32-px x-tiles, 4-row y-tiles -> 350 CTAs

    // stage 0 @100x100 (layers 0..4)
    conv_mma_t<4,2,32,4><<<gs0, 128, SMEM100>>>(s0a, nullptr, 0, emb, nullptr, 0, 2, s0b, 0, 0, 100, 100);
    conv_mma_t<4,2,32,4><<<gs0, 128, SMEM100>>>(s0b, nullptr, 1, nullptr, nullptr, 0, 0, s0c, 0, 1, 100, 100);
    conv_mma_t<4,2,32,4><<<gs0, 128, SMEM100>>>(s0c, nullptr, 2, s0b, nullptr, 0, 1, s0d, 0, 1, 100, 100);
    conv_mma_t<4,2,32,4><<<gs0, 128, SMEM100>>>(s0d, nullptr, 3, nullptr, nullptr, 0, 0, s0b, 0, 1, 100, 100);
    conv_mma_t<4,2,32,4><<<gs0, 128, SMEM100>>>(s0b, nullptr, 4, s0d, nullptr, 0, 1, s0c, 0, 1, 100, 100);

    // stage 1 @200x200 (layers 5..10)
    conv_mma_t<8,4,32,3><<<gs1, 256, SMEM200>>>(b1, nullptr, 5, nullptr, nullptr, 0, 0, b2, 0, 0, 200, 200);
    conv_mma_t<8,4,32,3><<<gs1, 256, SMEM200>>>(s0c, nullptr, 6, nullptr, nullptr, 1, 0, b4, 0, 0, 200, 200);
    in_rows_k<<<202, 256>>>(b4);
    in_stats_k<<<1, 64>>>();
    // L7: in = IN(b4)+b2 (fused), out b3
    conv_mma_t<8,4,32,3><<<gs1, 256, SMEM200>>>(b4, b2, 7, nullptr, nullptr, 2, 0, b3, 0, 1, 200, 200);
    // L8: in b3, add = IN(b4)+b2 (fused), out b1
    conv_mma_t<8,4,32,3><<<gs1, 256, SMEM200>>>(b3, nullptr, 8, b4, b2, 0, 3, b1, 0, 1, 200, 200);
    // L9: in b1, out b3
    conv_mma_t<8,4,32,3><<<gs1, 256, SMEM200>>>(b1, nullptr, 9, nullptr, nullptr, 0, 0, b3, 0, 1, 200, 200);
    // L10: in b3, add b1, out (CHW)
    conv_mma_t<8,4,32,3><<<gs1, 256, SMEM200>>>(b3, nullptr, 10, b1, nullptr, 0, 1, out, 1, 1, 200, 200);
}

// round 15
// speedup vs baseline: 1.0250x; 1.0250x over previous
#include <cuda_runtime.h>
#include <cuda_fp16.h>
#include <math.h>

#define G_TOT 2048

// ---------------- scratch (zero-initialized globals; halos never written) ----------------
__device__ __align__(128) float4 g_p0[2][G_TOT];
__device__ __align__(128) float4 g_p1[2][G_TOT];
__device__ __align__(128) float g_s0a[102*102*64];
__device__ __align__(128) float g_s0b[102*102*64];
__device__ __align__(128) float g_s0c[102*102*64];
__device__ __align__(128) float g_s0d[102*102*64];
__device__ __align__(128) float g_b1[202*202*64];
__device__ __align__(128) float g_b2[202*202*64];
__device__ __align__(128) float g_b3[202*202*64];
__device__ __align__(128) float g_b4[202*202*64];
__device__ __align__(128) unsigned g_wp[11*9*2048];   // swizzled fp16x2 weights
__device__ __align__(128) float g_part[202*512];
__device__ float g_stats[128];

#define MMA_F16(c0,c1,c2,c3,a0,a1,a2,a3,b0,b1) \
  asm("mma.sync.aligned.m16n8k16.row.col.f32.f16.f16.f32 " \
      "{%0,%1,%2,%3}, {%4,%5,%6,%7}, {%8,%9}, {%0,%1,%2,%3};" \
      : "+f"(c0),"+f"(c1),"+f"(c2),"+f"(c3) \
      : "r"(a0),"r"(a1),"r"(a2),"r"(a3),"r"(b0),"r"(b1))

// ---------------- gaussian preprocessing ----------------
__global__ void prep_k(const float* __restrict__ means, const float* __restrict__ cov,
                       const float* __restrict__ opac)
{
    int g = blockIdx.x * blockDim.x + threadIdx.x;
    if (g >= G_TOT) return;
    float mx = means[g*3+0], my = means[g*3+1], mz = means[g*3+2];
    bool pos = (mx >= -50.f) && (mx <= 50.f) && (my >= -50.f) && (my <= 50.f)
            && (mz >= -4.f)  && (mz <= 4.f);
    float c0 = cov[g*6+0], c1 = cov[g*6+1], c3 = cov[g*6+3];
    #pragma unroll
    for (int s = 0; s < 2; s++) {
        float H  = (s == 0) ? 100.f : 200.f;
        float sh = (s == 0) ? 1.f   : 2.f;
        float op = opac[g*2+s];
        bool mk = pos && (op > 0.05f);
        float u = -sh*my + 0.5f*H;
        float v = -sh*mx + 0.5f*H;
        float a  = sh*sh*c3 + 0.3f;
        float cc = sh*sh*c0 + 0.3f;
        float bb = sh*sh*c1;
        float det = fmaxf(a*cc - bb*bb, 1e-8f);
        float inv = 1.f/det;
        float ct = logf(255.f*fmaxf(op, 1e-20f));
        float rx = sqrtf(fmaxf(2.f*ct*a , 0.f));
        float ry = sqrtf(fmaxf(2.f*ct*cc, 0.f));
        if (!mk) rx = -1.f;
        g_p0[s][g] = make_float4(u, v, rx, ry);
        g_p1[s][g] = make_float4(cc*inv, -bb*inv, a*inv, op);
    }
}

__global__ void numg_k(const float* __restrict__ means, const float* __restrict__ opac,
                       float* __restrict__ out, int out_size)
{
    __shared__ int red[256];
    int tid = threadIdx.x;
    int cnt = 0;
    for (int g = tid; g < G_TOT; g += 256) {
        float mx = means[g*3], my = means[g*3+1], mz = means[g*3+2];
        bool pos = (mx >= -50.f) && (mx <= 50.f) && (my >= -50.f) && (my <= 50.f)
                && (mz >= -4.f) && (mz <= 4.f);
        if (pos) {
            if (opac[g*2+0] > 0.05f) cnt++;
            if (opac[g*2+1] > 0.05f) cnt++;
        }
    }
    red[tid] = cnt; __syncthreads();
    for (int st = 128; st > 0; st >>= 1) {
        if (tid < st) red[tid] += red[tid+st];
        __syncthreads();
    }
    if (tid == 0 && out_size > 64*200*200) out[64*200*200] = (float)red[0];
}

// ---------------- weight prep: fp16 + per-kst swizzled layout ----------------
__global__ void prep_w(const float* __restrict__ conv1w, const float* __restrict__ blkw,
                       const float* __restrict__ upw)
{
    int idx = blockIdx.x * 256 + threadIdx.x;
    if (idx >= 11*9*32*64) return;
    int co   = idx & 63;
    int pair = (idx >> 6) & 31;
    int t    = idx >> 11;
    int tap  = t % 9;
    int l    = t / 9;
    const float* src;
    if (l == 0)      src = conv1w;
    else if (l <= 4) src = blkw + (l-1)*36864;
    else if (l == 5) src = conv1w + 36864;
    else if (l == 6) src = upw;
    else             src = blkw + (l-3)*36864;
    float w0 = src[co*576 + (2*pair  )*9 + tap];
    float w1 = src[co*576 + (2*pair+1)*9 + tap];
    __half2 h = __floats2half2_rn(w0, w1);

    int kst  = pair >> 3;
    int pl_  = pair & 7;
    int qk   = pl_ & 3;
    int pgrp = pl_ >> 2;
    int qp   = co & 7;
    int n    = co >> 3;
    int slot = ((qp + 2*qk) & 7) + 8*qk;
    int dst  = (l*9 + tap)*2048 + kst*512 + (n>>2)*256 + pgrp*128 + slot*4 + (n&3);
    g_wp[dst] = *reinterpret_cast<unsigned*>(&h);
}

// ---------------- tiled ordered splatting -> padded NHWC (4 CTAs/tile, 16ch each) ------
__global__ void render_k(int s, const float* __restrict__ feats,
                         float* __restrict__ out, int H)
{
    const int W = H;
    __shared__ int s_list[G_TOT];
    __shared__ int s_wcnt[8];
    int tid = threadIdx.x;
    int lane = tid & 31, wid = tid >> 5;
    int tx0 = blockIdx.x * 16, ty0 = blockIdx.y * 16;
    int zc  = blockIdx.z;          // 0..3: channels 16*zc .. 16*zc+15
    float xmin = (float)tx0, xmax = (float)min(tx0 + 15, W - 1);
    float ymin = (float)ty0, ymax = (float)min(ty0 + 15, H - 1);

    int num = 0;
    for (int base = 0; base < G_TOT; base += 256) {
        int g = base + tid;
        float4 q = g_p0[s][g];
        bool ok = (q.z >= 0.f) &&
                  (q.x + q.z >= xmin) && (q.x - q.z <= xmax) &&
                  (q.y + q.w >= ymin) && (q.y - q.w <= ymax);
        unsigned m = __ballot_sync(0xffffffffu, ok);
        if (lane == 0) s_wcnt[wid] = __popc(m);
        __syncthreads();
        int off = num + __popc(m & ((1u << lane) - 1u));
        int tot = 0;
        #pragma unroll
        for (int w2 = 0; w2 < 8; w2++) {
            int c = s_wcnt[w2];
            if (w2 < wid) off += c;
            tot += c;
        }
        if (ok) s_list[off] = g;
        num += tot;
        __syncthreads();
    }

    int px = tx0 + (tid & 15);
    int py = ty0 + (tid >> 4);
    float fx = (float)px, fy = (float)py;
    float T = 1.f;
    float acc[16];
    #pragma unroll
    for (int d = 0; d < 16; d++) acc[d] = 0.f;

    for (int i = 0; i < num; i++) {
        int g = s_list[i];
        float4 q = g_p0[s][g];
        float4 r = g_p1[s][g];
        float dx = q.x - fx, dy = q.y - fy;
        float power = -0.5f*(r.x*dx*dx + r.z*dy*dy) - r.y*dx*dy;
        float alpha = fminf(r.w * expf(power), 0.99f);
        if (alpha >= (1.f/255.f) && power <= 0.f) {
            float wg = alpha * T;
            T *= (1.f - alpha);
            const float4* f4 = (const float4*)(feats + (size_t)g * 64 + zc * 16);
            #pragma unroll
            for (int j = 0; j < 4; j++) {
                float4 fv = __ldg(f4 + j);
                acc[4*j+0] += wg*fv.x;
                acc[4*j+1] += wg*fv.y;
                acc[4*j+2] += wg*fv.z;
                acc[4*j+3] += wg*fv.w;
            }
        }
    }
    if (px < W && py < H) {
        float4* o = (float4*)(out + (((size_t)(py+1))*(W+2) + (px+1))*64 + zc*16);
        #pragma unroll
        for (int j = 0; j < 4; j++)
            o[j] = make_float4(acc[4*j], acc[4*j+1], acc[4*j+2], acc[4*j+3]);
    }
}

// ---------------- conv3x3 64->64 via m16n8k16 fp16 (A hi/lo 2-term) ----------------
__device__ __forceinline__ void epi_store(float v0, float v1, int y, int px, int ch,
    const float* add, int add_pad, float* out, int out_chw, int relu, int H, int W)
{
    if (px >= W) return;
    if (add) {
        const float* ap = add_pad
            ? (add + (((size_t)(y+1))*(W+2) + px + 1)*64 + ch)
            : (add + ((size_t)y*W + px)*64 + ch);
        float2 t = *(const float2*)ap;
        v0 += t.x; v1 += t.y;
    }
    if (relu) { v0 = fmaxf(v0, 0.f); v1 = fmaxf(v1, 0.f); }
    if (out_chw) {
        out[(size_t)ch*H*W + (size_t)y*W + px]     = v0;
        out[(size_t)(ch+1)*H*W + (size_t)y*W + px] = v1;
    } else {
        *(float2*)(out + (((size_t)(y+1))*(W+2) + px + 1)*64 + ch) = make_float2(v0, v1);
    }
}

template<int NW, int ROWS, int TW, int MB>
__global__ void __launch_bounds__(NW*32, MB)
conv_mma_t(const float* __restrict__ in, int layer,
           const float* __restrict__ add, int add_pad,
           float* __restrict__ out, int out_chw, int relu,
           int H, int W)
{
    constexpr int NT  = NW*32;
    constexpr int RS  = TW + 4;
    constexpr int AP  = (ROWS + 2) * RS;
    constexpr int APP = ((AP % 32) == 0 || (AP % 32) == 16) ? AP + 8 : AP;  // ≡8/24 mod 32
    constexpr int SMA = 32 * APP;
    constexpr int WPR = NW / ROWS;
    constexpr int PXW = TW / WPR;
    constexpr int F   = PXW / 16;

    extern __shared__ unsigned smu[];
    unsigned* Ah = smu;
    unsigned* Al = smu + SMA;
    unsigned* Wb = smu + 2*SMA;      // 2 buffers x 2048

    int tid = threadIdx.x;
    int lane = tid & 31, wid = tid >> 5;
    int x0 = blockIdx.x * TW;
    int y0 = blockIdx.y * ROWS;
    int Wp = W + 2;

    for (int i = tid; i < 16*AP; i += NT) {
        int m  = i / AP;
        int rc = i - m * AP;
        int r = rc / RS;
        int c = rc - r * RS;
        float4 v = make_float4(0.f, 0.f, 0.f, 0.f);
        if (c < TW+2 && (x0 + c) < Wp)
            v = *(const float4*)(in + (((size_t)(y0 + r))*Wp + x0 + c)*64 + m*4);
        __half2 h0 = __floats2half2_rn(v.x, v.y);
        __half2 h1 = __floats2half2_rn(v.z, v.w);
        __half2 l0 = __floats2half2_rn(v.x - __low2float(h0), v.y - __high2float(h0));
        __half2 l1 = __floats2half2_rn(v.z - __low2float(h1), v.w - __high2float(h1));
        Ah[(2*m  )*APP + rc] = *reinterpret_cast<unsigned*>(&h0);
        Ah[(2*m+1)*APP + rc] = *reinterpret_cast<unsigned*>(&h1);
        Al[(2*m  )*APP + rc] = *reinterpret_cast<unsigned*>(&l0);
        Al[(2*m+1)*APP + rc] = *reinterpret_cast<unsigned*>(&l1);
    }

    int yl = wid / WPR;
    int xw = (wid % WPR) * PXW;
    int qp = lane >> 2;
    int qk = lane & 3;
    int slot4 = (((qp + 2*qk) & 7) + 8*qk) * 4;

    float acc[F][8][4];
    #pragma unroll
    for (int f = 0; f < F; f++)
        #pragma unroll
        for (int n = 0; n < 8; n++)
            #pragma unroll
            for (int j = 0; j < 4; j++) acc[f][n][j] = 0.f;

    #pragma unroll 1
    for (int tap = 0; tap < 9; tap++) {
        unsigned* Wc = Wb + (tap & 1) * 2048;
        const uint4* pw = (const uint4*)(g_wp + ((size_t)layer*9 + tap)*2048);
        for (int i = tid; i < 512; i += NT)
            *((uint4*)Wc + i) = pw[i];
        __syncthreads();

        int dy = tap / 3;
        int dx = tap - 3*dy;
        int abase = (yl + dy)*RS + xw + dx + qp;

        #pragma unroll
        for (int kst = 0; kst < 4; kst++) {
            int p0 = kst*8 + qk;
            int p1 = p0 + 4;
            unsigned ah[F][4], al[F][4];
            #pragma unroll
            for (int f = 0; f < F; f++) {
                int a0b = p0*APP + abase + f*16;
                int a1b = p1*APP + abase + f*16;
                ah[f][0] = Ah[a0b];  ah[f][1] = Ah[a0b+8];
                ah[f][2] = Ah[a1b];  ah[f][3] = Ah[a1b+8];
                al[f][0] = Al[a0b];  al[f][1] = Al[a0b+8];
                al[f][2] = Al[a1b];  al[f][3] = Al[a1b+8];
            }
            const unsigned* wk = Wc + kst*512;
            #pragma unroll
            for (int nb = 0; nb < 2; nb++) {
                uint4 H0 = *(const uint4*)(wk + nb*256 +       slot4);
                uint4 H1 = *(const uint4*)(wk + nb*256 + 128 + slot4);
                const unsigned* h0p = (const unsigned*)&H0;
                const unsigned* h1p = (const unsigned*)&H1;
                #pragma unroll
                for (int j = 0; j < 4; j++) {
                    int n = nb*4 + j;
                    unsigned w0 = h0p[j], w1 = h1p[j];
                    #pragma unroll
                    for (int f = 0; f < F; f++) {
                        MMA_F16(acc[f][n][0],acc[f][n][1],acc[f][n][2],acc[f][n][3],
                                ah[f][0],ah[f][1],ah[f][2],ah[f][3], w0,w1);
                        MMA_F16(acc[f][n][0],acc[f][n][1],acc[f][n][2],acc[f][n][3],
                                al[f][0],al[f][1],al[f][2],al[f][3], w0,w1);
                    }
                }
            }
        }
        __syncthreads();
    }

    int y = y0 + yl;
    #pragma unroll
    for (int n = 0; n < 8; n++) {
        int ch = n*8 + 2*qk;
        #pragma unroll
        for (int f = 0; f < F; f++) {
            epi_store(acc[f][n][0], acc[f][n][1], y, x0+xw+f*16+qp,   ch, add, add_pad, out, out_chw, relu, H, W);
            epi_store(acc[f][n][2], acc[f][n][3], y, x0+xw+f*16+qp+8, ch, add, add_pad, out, out_chw, relu, H, W);
        }
    }
}

#define SMEM100 ((2*32*152 + 2*2048)*4)
#define SMEM200 ((2*32*216 + 2*2048)*4)

// ---------------- bilinear 2x upsample, padded NHWC 102 -> 202 ----------------
__global__ void upsample_k(const float* __restrict__ in, float* __restrict__ out)
{
    int idx = blockIdx.x * 256 + threadIdx.x;
    if (idx >= 200*200*16) return;
    int ci4 = idx & 15;
    int p = idx >> 4;
    int x = p % 200, y = p / 200;
    float sx = 0.5f*x - 0.25f;
    float sy = 0.5f*y - 0.25f;
    float fx = floorf(sx), fy = floorf(sy);
    float tx = sx - fx, ty = sy - fy;
    int x0c = max((int)fx, 0), x1c = min((int)fx + 1, 99);
    int y0c = max((int)fy, 0), y1c = min((int)fy + 1, 99);
    float4 v00 = ((const float4*)(in + (((size_t)(y0c+1))*102 + x0c+1)*64))[ci4];
    float4 v01 = ((const float4*)(in + (((size_t)(y0c+1))*102 + x1c+1)*64))[ci4];
    float4 v10 = ((const float4*)(in + (((size_t)(y1c+1))*102 + x0c+1)*64))[ci4];
    float4 v11 = ((const float4*)(in + (((size_t)(y1c+1))*102 + x1c+1)*64))[ci4];
    float w00 = (1.f-ty)*(1.f-tx), w01 = (1.f-ty)*tx, w10 = ty*(1.f-tx), w11 = ty*tx;
    float4 r;
    r.x = w00*v00.x + w01*v01.x + w10*v10.x + w11*v11.x;
    r.y = w00*v00.y + w01*v01.y + w10*v10.y + w11*v11.y;
    r.z = w00*v00.z + w01*v01.z + w10*v10.z + w11*v11.z;
    r.w = w00*v00.w + w01*v01.w + w10*v10.w + w11*v11.w;
    ((float4*)(out + (((size_t)(y+1))*202 + x+1)*64))[ci4] = r;
}

// ---------------- instance norm (deterministic two-stage) ----------------
__global__ void in_rows_k(const float* __restrict__ x)   // grid 202, block 256
{
    int r = blockIdx.x;
    int c = threadIdx.x & 63;
    int q = threadIdx.x >> 6;
    const float* p = x + (size_t)r * 202 * 64;
    int pa = q * 51;
    int pb = min(pa + 51, 202);
    float s = 0.f, s2 = 0.f;
    for (int px = pa; px < pb; px++) {
        float v = p[px*64 + c];
        s += v; s2 += v*v;
    }
    g_part[(r*4 + q)*128 + c]      = s;
    g_part[(r*4 + q)*128 + 64 + c] = s2;
}

__global__ void in_stats_k()
{
    int c = threadIdx.x;
    float s = 0.f, s2 = 0.f;
    for (int r = 0; r < 808; r++) {
        s  += g_part[r*128 + c];
        s2 += g_part[r*128 + 64 + c];
    }
    float mu  = s * (1.f/40000.f);
    float var = s2 * (1.f/40000.f) - mu*mu;
    g_stats[c*2]   = mu;
    g_stats[c*2+1] = 1.f/sqrtf(var + 1e-5f);
}

__global__ void in_apply_k(const float* __restrict__ t, const float* __restrict__ addp,
                           float* __restrict__ out)
{
    int idx = blockIdx.x * 256 + threadIdx.x;
    if (idx >= 200*200*64) return;
    int ch = idx & 63;
    int p = idx >> 6;
    int x = p % 200, y = p / 200;
    size_t o = (((size_t)(y+1))*202 + x+1)*64 + ch;
    out[o] = (t[o] - g_stats[ch*2]) * g_stats[ch*2+1] + addp[o];
}

// ---------------- launch ----------------
extern "C" void kernel_launch(void* const* d_in, const int* in_sizes, int n_in,
                              void* d_out, int out_size)
{
    const float* features = (const float*)d_in[0];
    const float* means    = (const float*)d_in[1];
    const float* cov      = (const float*)d_in[2];
    const float* opac     = (const float*)d_in[3];
    const float* emb      = (const float*)d_in[4];
    const float* conv1w   = (const float*)d_in[5];
    const float* blkw     = (const float*)d_in[6];
    const float* upw      = (const float*)d_in[7];
    float* out = (float*)d_out;

    cudaFuncSetAttribute(conv_mma_t<4,2,32,4>, cudaFuncAttributeMaxDynamicSharedMemorySize, SMEM100);
    cudaFuncSetAttribute(conv_mma_t<8,4,32,3>, cudaFuncAttributeMaxDynamicSharedMemorySize, SMEM200);

    float *s0a,*s0b,*s0c,*s0d,*b1,*b2,*b3,*b4;
    cudaGetSymbolAddress((void**)&s0a, g_s0a);
    cudaGetSymbolAddress((void**)&s0b, g_s0b);
    cudaGetSymbolAddress((void**)&s0c, g_s0c);
    cudaGetSymbolAddress((void**)&s0d, g_s0d);
    cudaGetSymbolAddress((void**)&b1,  g_b1);
    cudaGetSymbolAddress((void**)&b2,  g_b2);
    cudaGetSymbolAddress((void**)&b3,  g_b3);
    cudaGetSymbolAddress((void**)&b4,  g_b4);

    prep_k<<<8, 256>>>(means, cov, opac);
    numg_k<<<1, 256>>>(means, opac, out, out_size);
    prep_w<<<792, 256>>>(conv1w, blkw, upw);
    render_k<<<dim3(7,7,4),   256>>>(0, features, s0a, 100);
    render_k<<<dim3(13,13,4), 256>>>(1, features, b1, 200);

    dim3 gs0(4, 50);   // 100²: 32-px x-tiles, 2-row y-tiles -> 200 CTAs @ 4/SM
    dim3 gs1(7, 50);   // 200²: 32-px x-tiles, 4-row y-tiles -> 350 CTAs @ 3/SM

    // stage 0 @100x100 (layers 0..4)
    conv_mma_t<4,2,32,4><<<gs0, 128, SMEM100>>>(s0a, 0, emb, 0, s0b, 0, 0, 100, 100);
    conv_mma_t<4,2,32,4><<<gs0, 128, SMEM100>>>(s0b, 1, nullptr, 1, s0c, 0, 1, 100, 100);
    conv_mma_t<4,2,32,4><<<gs0, 128, SMEM100>>>(s0c, 2, s0b, 1, s0d, 0, 1, 100, 100);
    conv_mma_t<4,2,32,4><<<gs0, 128, SMEM100>>>(s0d, 3, nullptr, 1, s0b, 0, 1, 100, 100);
    conv_mma_t<4,2,32,4><<<gs0, 128, SMEM100>>>(s0b, 4, s0d, 1, s0c, 0, 1, 100, 100);

    // stage 1 @200x200 (layers 5..10)
    conv_mma_t<8,4,32,3><<<gs1, 256, SMEM200>>>(b1, 5, nullptr, 1, b2, 0, 0, 200, 200);
    upsample_k<<<2500, 256>>>(s0c, b3);
    conv_mma_t<8,4,32,3><<<gs1, 256, SMEM200>>>(b3, 6, nullptr, 1, b4, 0, 0, 200, 200);
    in_rows_k<<<202, 256>>>(b4);
    in_stats_k<<<1, 64>>>();
    in_apply_k<<<10000, 256>>>(b4, b2, b1);
    conv_mma_t<8,4,32,3><<<gs1, 256, SMEM200>>>(b1, 7, nullptr, 1, b3, 0, 1, 200, 200);
    conv_mma_t<8,4,32,3><<<gs1, 256, SMEM200>>>(b3, 8, b1, 1, b4, 0, 1, 200, 200);
    conv_mma_t<8,4,32,3><<<gs1, 256, SMEM200>>>(b4, 9, nullptr, 1, b3, 0, 1, 200, 200);
    conv_mma_t<8,4,32,3><<<gs1, 256, SMEM200>>>(b3, 10, b4, 1, out, 1, 1, 200, 200);
}

// round 16
// speedup vs baseline: 1.1434x; 1.1155x over previous
#include <cuda_runtime.h>
#include <cuda_fp16.h>
#include <math.h>

#define G_TOT 2048

// ---------------- scratch (zero-initialized globals; halos never written) ----------------
__device__ __align__(128) float4 g_p0[2][G_TOT];
__device__ __align__(128) float4 g_p1[2][G_TOT];
__device__ __align__(128) float g_s0a[102*102*64];
__device__ __align__(128) float g_s0b[102*102*64];
__device__ __align__(128) float g_s0c[102*102*64];
__device__ __align__(128) float g_s0d[102*102*64];
__device__ __align__(128) float g_b1[202*202*64];
__device__ __align__(128) float g_b2[202*202*64];
__device__ __align__(128) float g_b3[202*202*64];
__device__ __align__(128) float g_b4[202*202*64];
__device__ __align__(128) unsigned g_wp[11*9*2048];   // swizzled fp16x2 weights
__device__ __align__(128) float g_part[202*128];
__device__ float g_stats[128];

#define MMA_F16(c0,c1,c2,c3,a0,a1,a2,a3,b0,b1) \
  asm("mma.sync.aligned.m16n8k16.row.col.f32.f16.f16.f32 " \
      "{%0,%1,%2,%3}, {%4,%5,%6,%7}, {%8,%9}, {%0,%1,%2,%3};" \
      : "+f"(c0),"+f"(c1),"+f"(c2),"+f"(c3) \
      : "r"(a0),"r"(a1),"r"(a2),"r"(a3),"r"(b0),"r"(b1))

// ---------------- gaussian preprocessing ----------------
__global__ void prep_k(const float* __restrict__ means, const float* __restrict__ cov,
                       const float* __restrict__ opac)
{
    int g = blockIdx.x * blockDim.x + threadIdx.x;
    if (g >= G_TOT) return;
    float mx = means[g*3+0], my = means[g*3+1], mz = means[g*3+2];
    bool pos = (mx >= -50.f) && (mx <= 50.f) && (my >= -50.f) && (my <= 50.f)
            && (mz >= -4.f)  && (mz <= 4.f);
    float c0 = cov[g*6+0], c1 = cov[g*6+1], c3 = cov[g*6+3];
    #pragma unroll
    for (int s = 0; s < 2; s++) {
        float H  = (s == 0) ? 100.f : 200.f;
        float sh = (s == 0) ? 1.f   : 2.f;
        float op = opac[g*2+s];
        bool mk = pos && (op > 0.05f);
        float u = -sh*my + 0.5f*H;
        float v = -sh*mx + 0.5f*H;
        float a  = sh*sh*c3 + 0.3f;
        float cc = sh*sh*c0 + 0.3f;
        float bb = sh*sh*c1;
        float det = fmaxf(a*cc - bb*bb, 1e-8f);
        float inv = 1.f/det;
        float ct = logf(255.f*fmaxf(op, 1e-20f));
        float rx = sqrtf(fmaxf(2.f*ct*a , 0.f));
        float ry = sqrtf(fmaxf(2.f*ct*cc, 0.f));
        if (!mk) rx = -1.f;
        g_p0[s][g] = make_float4(u, v, rx, ry);
        g_p1[s][g] = make_float4(cc*inv, -bb*inv, a*inv, op);
    }
}

__global__ void numg_k(const float* __restrict__ means, const float* __restrict__ opac,
                       float* __restrict__ out, int out_size)
{
    __shared__ int red[256];
    int tid = threadIdx.x;
    int cnt = 0;
    for (int g = tid; g < G_TOT; g += 256) {
        float mx = means[g*3], my = means[g*3+1], mz = means[g*3+2];
        bool pos = (mx >= -50.f) && (mx <= 50.f) && (my >= -50.f) && (my <= 50.f)
                && (mz >= -4.f) && (mz <= 4.f);
        if (pos) {
            if (opac[g*2+0] > 0.05f) cnt++;
            if (opac[g*2+1] > 0.05f) cnt++;
        }
    }
    red[tid] = cnt; __syncthreads();
    for (int st = 128; st > 0; st >>= 1) {
        if (tid < st) red[tid] += red[tid+st];
        __syncthreads();
    }
    if (tid == 0 && out_size > 64*200*200) out[64*200*200] = (float)red[0];
}

// ---------------- weight prep: fp16 + per-kst swizzled layout ----------------
__global__ void prep_w(const float* __restrict__ conv1w, const float* __restrict__ blkw,
                       const float* __restrict__ upw)
{
    int idx = blockIdx.x * 256 + threadIdx.x;
    if (idx >= 11*9*32*64) return;
    int co   = idx & 63;
    int pair = (idx >> 6) & 31;
    int t    = idx >> 11;
    int tap  = t % 9;
    int l    = t / 9;
    const float* src;
    if (l == 0)      src = conv1w;
    else if (l <= 4) src = blkw + (l-1)*36864;
    else if (l == 5) src = conv1w + 36864;
    else if (l == 6) src = upw;
    else             src = blkw + (l-3)*36864;
    float w0 = src[co*576 + (2*pair  )*9 + tap];
    float w1 = src[co*576 + (2*pair+1)*9 + tap];
    __half2 h = __floats2half2_rn(w0, w1);

    int kst  = pair >> 3;
    int pl_  = pair & 7;
    int qk   = pl_ & 3;
    int pgrp = pl_ >> 2;
    int qp   = co & 7;
    int n    = co >> 3;
    int slot = ((qp + 2*qk) & 7) + 8*qk;
    int dst  = (l*9 + tap)*2048 + kst*512 + (n>>2)*256 + pgrp*128 + slot*4 + (n&3);
    g_wp[dst] = *reinterpret_cast<unsigned*>(&h);
}

// ---------------- tiled ordered splatting -> padded NHWC (4 CTAs/tile, 16ch each) ------
__global__ void render_k(int s, const float* __restrict__ feats,
                         float* __restrict__ out, int H)
{
    const int W = H;
    __shared__ int s_list[G_TOT];
    __shared__ int s_wcnt[8];
    int tid = threadIdx.x;
    int lane = tid & 31, wid = tid >> 5;
    int tx0 = blockIdx.x * 16, ty0 = blockIdx.y * 16;
    int zc  = blockIdx.z;          // 0..3: channels 16*zc .. 16*zc+15
    float xmin = (float)tx0, xmax = (float)min(tx0 + 15, W - 1);
    float ymin = (float)ty0, ymax = (float)min(ty0 + 15, H - 1);

    int num = 0;
    for (int base = 0; base < G_TOT; base += 256) {
        int g = base + tid;
        float4 q = g_p0[s][g];
        bool ok = (q.z >= 0.f) &&
                  (q.x + q.z >= xmin) && (q.x - q.z <= xmax) &&
                  (q.y + q.w >= ymin) && (q.y - q.w <= ymax);
        unsigned m = __ballot_sync(0xffffffffu, ok);
        if (lane == 0) s_wcnt[wid] = __popc(m);
        __syncthreads();
        int off = num + __popc(m & ((1u << lane) - 1u));
        int tot = 0;
        #pragma unroll
        for (int w2 = 0; w2 < 8; w2++) {
            int c = s_wcnt[w2];
            if (w2 < wid) off += c;
            tot += c;
        }
        if (ok) s_list[off] = g;
        num += tot;
        __syncthreads();
    }

    int px = tx0 + (tid & 15);
    int py = ty0 + (tid >> 4);
    float fx = (float)px, fy = (float)py;
    float T = 1.f;
    float acc[16];
    #pragma unroll
    for (int d = 0; d < 16; d++) acc[d] = 0.f;

    for (int i = 0; i < num; i++) {
        int g = s_list[i];
        float4 q = g_p0[s][g];
        float4 r = g_p1[s][g];
        float dx = q.x - fx, dy = q.y - fy;
        float power = -0.5f*(r.x*dx*dx + r.z*dy*dy) - r.y*dx*dy;
        float alpha = fminf(r.w * expf(power), 0.99f);
        if (alpha >= (1.f/255.f) && power <= 0.f) {
            float wg = alpha * T;
            T *= (1.f - alpha);
            const float4* f4 = (const float4*)(feats + (size_t)g * 64 + zc * 16);
            #pragma unroll
            for (int j = 0; j < 4; j++) {
                float4 fv = __ldg(f4 + j);
                acc[4*j+0] += wg*fv.x;
                acc[4*j+1] += wg*fv.y;
                acc[4*j+2] += wg*fv.z;
                acc[4*j+3] += wg*fv.w;
            }
        }
    }
    if (px < W && py < H) {
        float4* o = (float4*)(out + (((size_t)(py+1))*(W+2) + (px+1))*64 + zc*16);
        #pragma unroll
        for (int j = 0; j < 4; j++)
            o[j] = make_float4(acc[4*j], acc[4*j+1], acc[4*j+2], acc[4*j+3]);
    }
}

// ---------------- conv3x3 64->64 via m16n8k16 fp16 (A hi/lo 2-term) ----------------
__device__ __forceinline__ void epi_store(float v0, float v1, int y, int px, int ch,
    const float* add, int add_pad, float* out, int out_chw, int relu, int H, int W)
{
    if (px >= W) return;
    if (add) {
        const float* ap = add_pad
            ? (add + (((size_t)(y+1))*(W+2) + px + 1)*64 + ch)
            : (add + ((size_t)y*W + px)*64 + ch);
        float2 t = *(const float2*)ap;
        v0 += t.x; v1 += t.y;
    }
    if (relu) { v0 = fmaxf(v0, 0.f); v1 = fmaxf(v1, 0.f); }
    if (out_chw) {
        out[(size_t)ch*H*W + (size_t)y*W + px]     = v0;
        out[(size_t)(ch+1)*H*W + (size_t)y*W + px] = v1;
    } else {
        *(float2*)(out + (((size_t)(y+1))*(W+2) + px + 1)*64 + ch) = make_float2(v0, v1);
    }
}

template<int NW, int ROWS, int TW, int MB>
__global__ void __launch_bounds__(NW*32, MB)
conv_mma_t(const float* __restrict__ in, int layer,
           const float* __restrict__ add, int add_pad,
           float* __restrict__ out, int out_chw, int relu,
           int H, int W)
{
    constexpr int NT  = NW*32;
    constexpr int RS  = TW + 4;
    constexpr int AP  = (ROWS + 2) * RS;
    constexpr int APP = ((AP % 32) == 0 || (AP % 32) == 16) ? AP + 8 : AP;  // ≡8/24 mod 32
    constexpr int SMA = 32 * APP;
    constexpr int WPR = NW / ROWS;
    constexpr int PXW = TW / WPR;
    constexpr int F   = PXW / 16;

    extern __shared__ unsigned smu[];
    unsigned* Ah = smu;
    unsigned* Al = smu + SMA;
    unsigned* Wb = smu + 2*SMA;      // 2 buffers x 2048

    int tid = threadIdx.x;
    int lane = tid & 31, wid = tid >> 5;
    int x0 = blockIdx.x * TW;
    int y0 = blockIdx.y * ROWS;
    int Wp = W + 2;

    for (int i = tid; i < 16*AP; i += NT) {
        int m  = i / AP;
        int rc = i - m * AP;
        int r = rc / RS;
        int c = rc - r * RS;
        float4 v = make_float4(0.f, 0.f, 0.f, 0.f);
        if (c < TW+2 && (x0 + c) < Wp)
            v = *(const float4*)(in + (((size_t)(y0 + r))*Wp + x0 + c)*64 + m*4);
        __half2 h0 = __floats2half2_rn(v.x, v.y);
        __half2 h1 = __floats2half2_rn(v.z, v.w);
        __half2 l0 = __floats2half2_rn(v.x - __low2float(h0), v.y - __high2float(h0));
        __half2 l1 = __floats2half2_rn(v.z - __low2float(h1), v.w - __high2float(h1));
        Ah[(2*m  )*APP + rc] = *reinterpret_cast<unsigned*>(&h0);
        Ah[(2*m+1)*APP + rc] = *reinterpret_cast<unsigned*>(&h1);
        Al[(2*m  )*APP + rc] = *reinterpret_cast<unsigned*>(&l0);
        Al[(2*m+1)*APP + rc] = *reinterpret_cast<unsigned*>(&l1);
    }

    int yl = wid / WPR;
    int xw = (wid % WPR) * PXW;
    int qp = lane >> 2;
    int qk = lane & 3;
    int slot4 = (((qp + 2*qk) & 7) + 8*qk) * 4;

    float acc[F][8][4];
    #pragma unroll
    for (int f = 0; f < F; f++)
        #pragma unroll
        for (int n = 0; n < 8; n++)
            #pragma unroll
            for (int j = 0; j < 4; j++) acc[f][n][j] = 0.f;

    #pragma unroll 1
    for (int tap = 0; tap < 9; tap++) {
        unsigned* Wc = Wb + (tap & 1) * 2048;
        const uint4* pw = (const uint4*)(g_wp + ((size_t)layer*9 + tap)*2048);
        for (int i = tid; i < 512; i += NT)
            *((uint4*)Wc + i) = pw[i];
        __syncthreads();

        int dy = tap / 3;
        int dx = tap - 3*dy;
        int abase = (yl + dy)*RS + xw + dx + qp;

        #pragma unroll
        for (int kst = 0; kst < 4; kst++) {
            int p0 = kst*8 + qk;
            int p1 = p0 + 4;
            unsigned ah[F][4], al[F][4];
            #pragma unroll
            for (int f = 0; f < F; f++) {
                int a0b = p0*APP + abase + f*16;
                int a1b = p1*APP + abase + f*16;
                ah[f][0] = Ah[a0b];  ah[f][1] = Ah[a0b+8];
                ah[f][2] = Ah[a1b];  ah[f][3] = Ah[a1b+8];
                al[f][0] = Al[a0b];  al[f][1] = Al[a0b+8];
                al[f][2] = Al[a1b];  al[f][3] = Al[a1b+8];
            }
            const unsigned* wk = Wc + kst*512;
            #pragma unroll
            for (int nb = 0; nb < 2; nb++) {
                uint4 H0 = *(const uint4*)(wk + nb*256 +       slot4);
                uint4 H1 = *(const uint4*)(wk + nb*256 + 128 + slot4);
                const unsigned* h0p = (const unsigned*)&H0;
                const unsigned* h1p = (const unsigned*)&H1;
                #pragma unroll
                for (int j = 0; j < 4; j++) {
                    int n = nb*4 + j;
                    unsigned w0 = h0p[j], w1 = h1p[j];
                    #pragma unroll
                    for (int f = 0; f < F; f++) {
                        MMA_F16(acc[f][n][0],acc[f][n][1],acc[f][n][2],acc[f][n][3],
                                ah[f][0],ah[f][1],ah[f][2],ah[f][3], w0,w1);
                        MMA_F16(acc[f][n][0],acc[f][n][1],acc[f][n][2],acc[f][n][3],
                                al[f][0],al[f][1],al[f][2],al[f][3], w0,w1);
                    }
                }
            }
        }
        __syncthreads();
    }

    int y = y0 + yl;
    #pragma unroll
    for (int n = 0; n < 8; n++) {
        int ch = n*8 + 2*qk;
        #pragma unroll
        for (int f = 0; f < F; f++) {
            epi_store(acc[f][n][0], acc[f][n][1], y, x0+xw+f*16+qp,   ch, add, add_pad, out, out_chw, relu, H, W);
            epi_store(acc[f][n][2], acc[f][n][3], y, x0+xw+f*16+qp+8, ch, add, add_pad, out, out_chw, relu, H, W);
        }
    }
}

#define SMEM100 ((2*32*152 + 2*2048)*4)
#define SMEM200 ((2*32*216 + 2*2048)*4)

// ---------------- bilinear 2x upsample, padded NHWC 102 -> 202 ----------------
__global__ void upsample_k(const float* __restrict__ in, float* __restrict__ out)
{
    int idx = blockIdx.x * 256 + threadIdx.x;
    if (idx >= 200*200*16) return;
    int ci4 = idx & 15;
    int p = idx >> 4;
    int x = p % 200, y = p / 200;
    float sx = 0.5f*x - 0.25f;
    float sy = 0.5f*y - 0.25f;
    float fx = floorf(sx), fy = floorf(sy);
    float tx = sx - fx, ty = sy - fy;
    int x0c = max((int)fx, 0), x1c = min((int)fx + 1, 99);
    int y0c = max((int)fy, 0), y1c = min((int)fy + 1, 99);
    float4 v00 = ((const float4*)(in + (((size_t)(y0c+1))*102 + x0c+1)*64))[ci4];
    float4 v01 = ((const float4*)(in + (((size_t)(y0c+1))*102 + x1c+1)*64))[ci4];
    float4 v10 = ((const float4*)(in + (((size_t)(y1c+1))*102 + x0c+1)*64))[ci4];
    float4 v11 = ((const float4*)(in + (((size_t)(y1c+1))*102 + x1c+1)*64))[ci4];
    float w00 = (1.f-ty)*(1.f-tx), w01 = (1.f-ty)*tx, w10 = ty*(1.f-tx), w11 = ty*tx;
    float4 r;
    r.x = w00*v00.x + w01*v01.x + w10*v10.x + w11*v11.x;
    r.y = w00*v00.y + w01*v01.y + w10*v10.y + w11*v11.y;
    r.z = w00*v00.z + w01*v01.z + w10*v10.z + w11*v11.z;
    r.w = w00*v00.w + w01*v01.w + w10*v10.w + w11*v11.w;
    ((float4*)(out + (((size_t)(y+1))*202 + x+1)*64))[ci4] = r;
}

// ---------------- instance norm (deterministic two-stage, R13 form) ----------------
__global__ void in_rows_k(const float* __restrict__ x)
{
    int r = blockIdx.x;
    int c = threadIdx.x;
    const float* p = x + (size_t)r * 202 * 64;
    float s = 0.f, s2 = 0.f;
    for (int px = 0; px < 202; px++) {
        float v = p[px*64 + c];
        s += v; s2 += v*v;
    }
    g_part[r*128 + c]      = s;
    g_part[r*128 + 64 + c] = s2;
}

__global__ void in_stats_k()
{
    int c = threadIdx.x;
    float s = 0.f, s2 = 0.f;
    for (int r = 0; r < 202; r++) {
        s  += g_part[r*128 + c];
        s2 += g_part[r*128 + 64 + c];
    }
    float mu  = s * (1.f/40000.f);
    float var = s2 * (1.f/40000.f) - mu*mu;
    g_stats[c*2]   = mu;
    g_stats[c*2+1] = 1.f/sqrtf(var + 1e-5f);
}

__global__ void in_apply_k(const float* __restrict__ t, const float* __restrict__ addp,
                           float* __restrict__ out)
{
    int idx = blockIdx.x * 256 + threadIdx.x;
    if (idx >= 200*200*64) return;
    int ch = idx & 63;
    int p = idx >> 6;
    int x = p % 200, y = p / 200;
    size_t o = (((size_t)(y+1))*202 + x+1)*64 + ch;
    out[o] = (t[o] - g_stats[ch*2]) * g_stats[ch*2+1] + addp[o];
}

// ---------------- launch ----------------
extern "C" void kernel_launch(void* const* d_in, const int* in_sizes, int n_in,
                              void* d_out, int out_size)
{
    const float* features = (const float*)d_in[0];
    const float* means    = (const float*)d_in[1];
    const float* cov      = (const float*)d_in[2];
    const float* opac     = (const float*)d_in[3];
    const float* emb      = (const float*)d_in[4];
    const float* conv1w   = (const float*)d_in[5];
    const float* blkw     = (const float*)d_in[6];
    const float* upw      = (const float*)d_in[7];
    float* out = (float*)d_out;

    cudaFuncSetAttribute(conv_mma_t<4,2,32,4>, cudaFuncAttributeMaxDynamicSharedMemorySize, SMEM100);
    cudaFuncSetAttribute(conv_mma_t<8,4,32,3>, cudaFuncAttributeMaxDynamicSharedMemorySize, SMEM200);

    // lazily-created side stream + fork/join events (host resources only, created once)
    static cudaStream_t sB = nullptr;
    static cudaEvent_t  eFork = nullptr, eJoin = nullptr;
    if (!sB) {
        cudaStreamCreateWithFlags(&sB, cudaStreamNonBlocking);
        cudaEventCreateWithFlags(&eFork, cudaEventDisableTiming);
        cudaEventCreateWithFlags(&eJoin, cudaEventDisableTiming);
    }

    float *s0a,*s0b,*s0c,*s0d,*b1,*b2,*b3,*b4;
    cudaGetSymbolAddress((void**)&s0a, g_s0a);
    cudaGetSymbolAddress((void**)&s0b, g_s0b);
    cudaGetSymbolAddress((void**)&s0c, g_s0c);
    cudaGetSymbolAddress((void**)&s0d, g_s0d);
    cudaGetSymbolAddress((void**)&b1,  g_b1);
    cudaGetSymbolAddress((void**)&b2,  g_b2);
    cudaGetSymbolAddress((void**)&b3,  g_b3);
    cudaGetSymbolAddress((void**)&b4,  g_b4);

    // main stream (0): prep + stage-0 path
    prep_k<<<8, 256>>>(means, cov, opac);
    numg_k<<<1, 256>>>(means, opac, out, out_size);
    prep_w<<<792, 256>>>(conv1w, blkw, upw);

    // fork: side stream does render_s1 + L5 (independent of stage-0 chain)
    cudaEventRecord(eFork, 0);
    cudaStreamWaitEvent(sB, eFork, 0);

    render_k<<<dim3(7,7,4), 256>>>(0, features, s0a, 100);           // stream 0
    render_k<<<dim3(13,13,4), 256, 0, sB>>>(1, features, b1, 200);   // stream B

    dim3 gs0(4, 50);
    dim3 gs1(7, 50);

    // stage 0 @100x100 (layers 0..4) — stream 0
    conv_mma_t<4,2,32,4><<<gs0, 128, SMEM100>>>(s0a, 0, emb, 0, s0b, 0, 0, 100, 100);
    conv_mma_t<4,2,32,4><<<gs0, 128, SMEM100>>>(s0b, 1, nullptr, 1, s0c, 0, 1, 100, 100);
    conv_mma_t<4,2,32,4><<<gs0, 128, SMEM100>>>(s0c, 2, s0b, 1, s0d, 0, 1, 100, 100);
    conv_mma_t<4,2,32,4><<<gs0, 128, SMEM100>>>(s0d, 3, nullptr, 1, s0b, 0, 1, 100, 100);
    conv_mma_t<4,2,32,4><<<gs0, 128, SMEM100>>>(s0b, 4, s0d, 1, s0c, 0, 1, 100, 100);

    // L5 on stream B (bev1 conv, needs b1 + weights only)
    conv_mma_t<8,4,32,3><<<gs1, 256, SMEM200, sB>>>(b1, 5, nullptr, 1, b2, 0, 0, 200, 200);
    cudaEventRecord(eJoin, sB);

    // stage-1 head on stream 0
    upsample_k<<<2500, 256>>>(s0c, b3);
    conv_mma_t<8,4,32,3><<<gs1, 256, SMEM200>>>(b3, 6, nullptr, 1, b4, 0, 0, 200, 200);
    in_rows_k<<<202, 64>>>(b4);
    in_stats_k<<<1, 64>>>();

    // join: in_apply needs b2 (stream B) + stats (stream 0)
    cudaStreamWaitEvent(0, eJoin, 0);
    in_apply_k<<<10000, 256>>>(b4, b2, b1);

    conv_mma_t<8,4,32,3><<<gs1, 256, SMEM200>>>(b1, 7, nullptr, 1, b3, 0, 1, 200, 200);
    conv_mma_t<8,4,32,3><<<gs1, 256, SMEM200>>>(b3, 8, b1, 1, b4, 0, 1, 200, 200);
    conv_mma_t<8,4,32,3><<<gs1, 256, SMEM200>>>(b4, 9, nullptr, 1, b3, 0, 1, 200, 200);
    conv_mma_t<8,4,32,3><<<gs1, 256, SMEM200>>>(b3, 10, b4, 1, out, 1, 1, 200, 200);
}

// round 17
// speedup vs baseline: 1.1517x; 1.0073x over previous
#include <cuda_runtime.h>
#include <cuda_fp16.h>
#include <math.h>

#define G_TOT 2048

// ---------------- scratch (zero-initialized globals; halos never written) ----------------
__device__ __align__(128) float4 g_p0[2][G_TOT];
__device__ __align__(128) float4 g_p1[2][G_TOT];
__device__ __align__(128) float g_s0a[102*102*64];
__device__ __align__(128) float g_s0b[102*102*64];
__device__ __align__(128) float g_s0c[102*102*64];
__device__ __align__(128) float g_s0d[102*102*64];
__device__ __align__(128) float g_b1[202*202*64];
__device__ __align__(128) float g_b2[202*202*64];
__device__ __align__(128) float g_b3[202*202*64];
__device__ __align__(128) float g_b4[202*202*64];
__device__ __align__(128) unsigned g_wp[11*9*2048];   // swizzled fp16x2 weights
__device__ __align__(128) float g_part[202*512];
__device__ float g_stats[128];

#define MMA_F16(c0,c1,c2,c3,a0,a1,a2,a3,b0,b1) \
  asm("mma.sync.aligned.m16n8k16.row.col.f32.f16.f16.f32 " \
      "{%0,%1,%2,%3}, {%4,%5,%6,%7}, {%8,%9}, {%0,%1,%2,%3};" \
      : "+f"(c0),"+f"(c1),"+f"(c2),"+f"(c3) \
      : "r"(a0),"r"(a1),"r"(a2),"r"(a3),"r"(b0),"r"(b1))

// ---------------- gaussian preprocessing ----------------
__global__ void prep_k(const float* __restrict__ means, const float* __restrict__ cov,
                       const float* __restrict__ opac)
{
    int g = blockIdx.x * blockDim.x + threadIdx.x;
    if (g >= G_TOT) return;
    float mx = means[g*3+0], my = means[g*3+1], mz = means[g*3+2];
    bool pos = (mx >= -50.f) && (mx <= 50.f) && (my >= -50.f) && (my <= 50.f)
            && (mz >= -4.f)  && (mz <= 4.f);
    float c0 = cov[g*6+0], c1 = cov[g*6+1], c3 = cov[g*6+3];
    #pragma unroll
    for (int s = 0; s < 2; s++) {
        float H  = (s == 0) ? 100.f : 200.f;
        float sh = (s == 0) ? 1.f   : 2.f;
        float op = opac[g*2+s];
        bool mk = pos && (op > 0.05f);
        float u = -sh*my + 0.5f*H;
        float v = -sh*mx + 0.5f*H;
        float a  = sh*sh*c3 + 0.3f;
        float cc = sh*sh*c0 + 0.3f;
        float bb = sh*sh*c1;
        float det = fmaxf(a*cc - bb*bb, 1e-8f);
        float inv = 1.f/det;
        float ct = logf(255.f*fmaxf(op, 1e-20f));
        float rx = sqrtf(fmaxf(2.f*ct*a , 0.f));
        float ry = sqrtf(fmaxf(2.f*ct*cc, 0.f));
        if (!mk) rx = -1.f;
        g_p0[s][g] = make_float4(u, v, rx, ry);
        g_p1[s][g] = make_float4(cc*inv, -bb*inv, a*inv, op);
    }
}

__global__ void numg_k(const float* __restrict__ means, const float* __restrict__ opac,
                       float* __restrict__ out, int out_size)
{
    __shared__ int red[256];
    int tid = threadIdx.x;
    int cnt = 0;
    for (int g = tid; g < G_TOT; g += 256) {
        float mx = means[g*3], my = means[g*3+1], mz = means[g*3+2];
        bool pos = (mx >= -50.f) && (mx <= 50.f) && (my >= -50.f) && (my <= 50.f)
                && (mz >= -4.f) && (mz <= 4.f);
        if (pos) {
            if (opac[g*2+0] > 0.05f) cnt++;
            if (opac[g*2+1] > 0.05f) cnt++;
        }
    }
    red[tid] = cnt; __syncthreads();
    for (int st = 128; st > 0; st >>= 1) {
        if (tid < st) red[tid] += red[tid+st];
        __syncthreads();
    }
    if (tid == 0 && out_size > 64*200*200) out[64*200*200] = (float)red[0];
}

// ---------------- weight prep: fp16 + per-kst swizzled layout ----------------
__global__ void prep_w(const float* __restrict__ conv1w, const float* __restrict__ blkw,
                       const float* __restrict__ upw)
{
    int idx = blockIdx.x * 256 + threadIdx.x;
    if (idx >= 11*9*32*64) return;
    int co   = idx & 63;
    int pair = (idx >> 6) & 31;
    int t    = idx >> 11;
    int tap  = t % 9;
    int l    = t / 9;
    const float* src;
    if (l == 0)      src = conv1w;
    else if (l <= 4) src = blkw + (l-1)*36864;
    else if (l == 5) src = conv1w + 36864;
    else if (l == 6) src = upw;
    else             src = blkw + (l-3)*36864;
    float w0 = src[co*576 + (2*pair  )*9 + tap];
    float w1 = src[co*576 + (2*pair+1)*9 + tap];
    __half2 h = __floats2half2_rn(w0, w1);

    int kst  = pair >> 3;
    int pl_  = pair & 7;
    int qk   = pl_ & 3;
    int pgrp = pl_ >> 2;
    int qp   = co & 7;
    int n    = co >> 3;
    int slot = ((qp + 2*qk) & 7) + 8*qk;
    int dst  = (l*9 + tap)*2048 + kst*512 + (n>>2)*256 + pgrp*128 + slot*4 + (n&3);
    g_wp[dst] = *reinterpret_cast<unsigned*>(&h);
}

// ---------------- tiled ordered splatting -> padded NHWC (4 CTAs/tile, 16ch each) ------
__global__ void render_k(int s, const float* __restrict__ feats,
                         float* __restrict__ out, int H)
{
    const int W = H;
    __shared__ int s_list[G_TOT];
    __shared__ int s_wcnt[8];
    int tid = threadIdx.x;
    int lane = tid & 31, wid = tid >> 5;
    int tx0 = blockIdx.x * 16, ty0 = blockIdx.y * 16;
    int zc  = blockIdx.z;          // 0..3: channels 16*zc .. 16*zc+15
    float xmin = (float)tx0, xmax = (float)min(tx0 + 15, W - 1);
    float ymin = (float)ty0, ymax = (float)min(ty0 + 15, H - 1);

    int num = 0;
    for (int base = 0; base < G_TOT; base += 256) {
        int g = base + tid;
        float4 q = g_p0[s][g];
        bool ok = (q.z >= 0.f) &&
                  (q.x + q.z >= xmin) && (q.x - q.z <= xmax) &&
                  (q.y + q.w >= ymin) && (q.y - q.w <= ymax);
        unsigned m = __ballot_sync(0xffffffffu, ok);
        if (lane == 0) s_wcnt[wid] = __popc(m);
        __syncthreads();
        int off = num + __popc(m & ((1u << lane) - 1u));
        int tot = 0;
        #pragma unroll
        for (int w2 = 0; w2 < 8; w2++) {
            int c = s_wcnt[w2];
            if (w2 < wid) off += c;
            tot += c;
        }
        if (ok) s_list[off] = g;
        num += tot;
        __syncthreads();
    }

    int px = tx0 + (tid & 15);
    int py = ty0 + (tid >> 4);
    float fx = (float)px, fy = (float)py;
    float T = 1.f;
    float acc[16];
    #pragma unroll
    for (int d = 0; d < 16; d++) acc[d] = 0.f;

    for (int i = 0; i < num; i++) {
        int g = s_list[i];
        float4 q = g_p0[s][g];
        float4 r = g_p1[s][g];
        float dx = q.x - fx, dy = q.y - fy;
        float power = -0.5f*(r.x*dx*dx + r.z*dy*dy) - r.y*dx*dy;
        float alpha = fminf(r.w * expf(power), 0.99f);
        if (alpha >= (1.f/255.f) && power <= 0.f) {
            float wg = alpha * T;
            T *= (1.f - alpha);
            const float4* f4 = (const float4*)(feats + (size_t)g * 64 + zc * 16);
            #pragma unroll
            for (int j = 0; j < 4; j++) {
                float4 fv = __ldg(f4 + j);
                acc[4*j+0] += wg*fv.x;
                acc[4*j+1] += wg*fv.y;
                acc[4*j+2] += wg*fv.z;
                acc[4*j+3] += wg*fv.w;
            }
        }
    }
    if (px < W && py < H) {
        float4* o = (float4*)(out + (((size_t)(py+1))*(W+2) + (px+1))*64 + zc*16);
        #pragma unroll
        for (int j = 0; j < 4; j++)
            o[j] = make_float4(acc[4*j], acc[4*j+1], acc[4*j+2], acc[4*j+3]);
    }
}

// ---------------- conv3x3 64->64 via m16n8k16 fp16 (A hi/lo 2-term) ----------------
// NB template: 2 = all 64 co per CTA; 1 = 32 co per CTA (blockIdx.z selects half)
__device__ __forceinline__ void epi_store(float v0, float v1, int y, int px, int ch,
    const float* add, int add_pad, float* out, int out_chw, int relu, int H, int W)
{
    if (px >= W) return;
    if (add) {
        const float* ap = add_pad
            ? (add + (((size_t)(y+1))*(W+2) + px + 1)*64 + ch)
            : (add + ((size_t)y*W + px)*64 + ch);
        float2 t = *(const float2*)ap;
        v0 += t.x; v1 += t.y;
    }
    if (relu) { v0 = fmaxf(v0, 0.f); v1 = fmaxf(v1, 0.f); }
    if (out_chw) {
        out[(size_t)ch*H*W + (size_t)y*W + px]     = v0;
        out[(size_t)(ch+1)*H*W + (size_t)y*W + px] = v1;
    } else {
        *(float2*)(out + (((size_t)(y+1))*(W+2) + px + 1)*64 + ch) = make_float2(v0, v1);
    }
}

template<int NW, int ROWS, int TW, int MB, int NB>
__global__ void __launch_bounds__(NW*32, MB)
conv_mma_t(const float* __restrict__ in, int layer,
           const float* __restrict__ add, int add_pad,
           float* __restrict__ out, int out_chw, int relu,
           int H, int W)
{
    constexpr int NT  = NW*32;
    constexpr int RS  = TW + 4;
    constexpr int AP  = (ROWS + 2) * RS;
    constexpr int APP = ((AP % 32) == 0 || (AP % 32) == 16) ? AP + 8 : AP;  // ≡8/24 mod 32
    constexpr int SMA = 32 * APP;
    constexpr int WPR = NW / ROWS;
    constexpr int PXW = TW / WPR;
    constexpr int F   = PXW / 16;

    extern __shared__ unsigned smu[];
    unsigned* Ah = smu;
    unsigned* Al = smu + SMA;
    unsigned* Wb = smu + 2*SMA;      // 2 buffers x 2048

    int tid = threadIdx.x;
    int lane = tid & 31, wid = tid >> 5;
    int x0 = blockIdx.x * TW;
    int y0 = blockIdx.y * ROWS;
    int nb0 = (NB == 2) ? 0 : (int)blockIdx.z;
    int Wp = W + 2;

    for (int i = tid; i < 16*AP; i += NT) {
        int m  = i / AP;
        int rc = i - m * AP;
        int r = rc / RS;
        int c = rc - r * RS;
        float4 v = make_float4(0.f, 0.f, 0.f, 0.f);
        if (c < TW+2 && (x0 + c) < Wp)
            v = *(const float4*)(in + (((size_t)(y0 + r))*Wp + x0 + c)*64 + m*4);
        __half2 h0 = __floats2half2_rn(v.x, v.y);
        __half2 h1 = __floats2half2_rn(v.z, v.w);
        __half2 l0 = __floats2half2_rn(v.x - __low2float(h0), v.y - __high2float(h0));
        __half2 l1 = __floats2half2_rn(v.z - __low2float(h1), v.w - __high2float(h1));
        Ah[(2*m  )*APP + rc] = *reinterpret_cast<unsigned*>(&h0);
        Ah[(2*m+1)*APP + rc] = *reinterpret_cast<unsigned*>(&h1);
        Al[(2*m  )*APP + rc] = *reinterpret_cast<unsigned*>(&l0);
        Al[(2*m+1)*APP + rc] = *reinterpret_cast<unsigned*>(&l1);
    }

    int yl = wid / WPR;
    int xw = (wid % WPR) * PXW;
    int qp = lane >> 2;
    int qk = lane & 3;
    int slot4 = (((qp + 2*qk) & 7) + 8*qk) * 4;

    float acc[F][4*NB][4];
    #pragma unroll
    for (int f = 0; f < F; f++)
        #pragma unroll
        for (int n = 0; n < 4*NB; n++)
            #pragma unroll
            for (int j = 0; j < 4; j++) acc[f][n][j] = 0.f;

    #pragma unroll 1
    for (int tap = 0; tap < 9; tap++) {
        unsigned* Wc = Wb + (tap & 1) * 2048;
        const uint4* pw = (const uint4*)(g_wp + ((size_t)layer*9 + tap)*2048);
        for (int i = tid; i < 512; i += NT)
            *((uint4*)Wc + i) = pw[i];
        __syncthreads();

        int dy = tap / 3;
        int dx = tap - 3*dy;
        int abase = (yl + dy)*RS + xw + dx + qp;

        #pragma unroll
        for (int kst = 0; kst < 4; kst++) {
            int p0 = kst*8 + qk;
            int p1 = p0 + 4;
            unsigned ah[F][4], al[F][4];
            #pragma unroll
            for (int f = 0; f < F; f++) {
                int a0b = p0*APP + abase + f*16;
                int a1b = p1*APP + abase + f*16;
                ah[f][0] = Ah[a0b];  ah[f][1] = Ah[a0b+8];
                ah[f][2] = Ah[a1b];  ah[f][3] = Ah[a1b+8];
                al[f][0] = Al[a0b];  al[f][1] = Al[a0b+8];
                al[f][2] = Al[a1b];  al[f][3] = Al[a1b+8];
            }
            const unsigned* wk = Wc + kst*512;
            #pragma unroll
            for (int nb = 0; nb < NB; nb++) {
                int nbe = nb0 + nb;
                uint4 H0 = *(const uint4*)(wk + nbe*256 +       slot4);
                uint4 H1 = *(const uint4*)(wk + nbe*256 + 128 + slot4);
                const unsigned* h0p = (const unsigned*)&H0;
                const unsigned* h1p = (const unsigned*)&H1;
                #pragma unroll
                for (int j = 0; j < 4; j++) {
                    int n = nb*4 + j;
                    unsigned w0 = h0p[j], w1 = h1p[j];
                    #pragma unroll
                    for (int f = 0; f < F; f++) {
                        MMA_F16(acc[f][n][0],acc[f][n][1],acc[f][n][2],acc[f][n][3],
                                ah[f][0],ah[f][1],ah[f][2],ah[f][3], w0,w1);
                        MMA_F16(acc[f][n][0],acc[f][n][1],acc[f][n][2],acc[f][n][3],
                                al[f][0],al[f][1],al[f][2],al[f][3], w0,w1);
                    }
                }
            }
        }
        __syncthreads();
    }

    int y = y0 + yl;
    #pragma unroll
    for (int nb = 0; nb < NB; nb++) {
        int nbe = nb0 + nb;
        #pragma unroll
        for (int j = 0; j < 4; j++) {
            int ch = (nbe*4 + j)*8 + 2*qk;
            int n  = nb*4 + j;
            #pragma unroll
            for (int f = 0; f < F; f++) {
                epi_store(acc[f][n][0], acc[f][n][1], y, x0+xw+f*16+qp,   ch, add, add_pad, out, out_chw, relu, H, W);
                epi_store(acc[f][n][2], acc[f][n][3], y, x0+xw+f*16+qp+8, ch, add, add_pad, out, out_chw, relu, H, W);
            }
        }
    }
}

#define SMEM100 ((2*32*152 + 2*2048)*4)
#define SMEM200 ((2*32*216 + 2*2048)*4)

// ---------------- bilinear 2x upsample, padded NHWC 102 -> 202 ----------------
__global__ void upsample_k(const float* __restrict__ in, float* __restrict__ out)
{
    int idx = blockIdx.x * 256 + threadIdx.x;
    if (idx >= 200*200*16) return;
    int ci4 = idx & 15;
    int p = idx >> 4;
    int x = p % 200, y = p / 200;
    float sx = 0.5f*x - 0.25f;
    float sy = 0.5f*y - 0.25f;
    float fx = floorf(sx), fy = floorf(sy);
    float tx = sx - fx, ty = sy - fy;
    int x0c = max((int)fx, 0), x1c = min((int)fx + 1, 99);
    int y0c = max((int)fy, 0), y1c = min((int)fy + 1, 99);
    float4 v00 = ((const float4*)(in + (((size_t)(y0c+1))*102 + x0c+1)*64))[ci4];
    float4 v01 = ((const float4*)(in + (((size_t)(y0c+1))*102 + x1c+1)*64))[ci4];
    float4 v10 = ((const float4*)(in + (((size_t)(y1c+1))*102 + x0c+1)*64))[ci4];
    float4 v11 = ((const float4*)(in + (((size_t)(y1c+1))*102 + x1c+1)*64))[ci4];
    float w00 = (1.f-ty)*(1.f-tx), w01 = (1.f-ty)*tx, w10 = ty*(1.f-tx), w11 = ty*tx;
    float4 r;
    r.x = w00*v00.x + w01*v01.x + w10*v10.x + w11*v11.x;
    r.y = w00*v00.y + w01*v01.y + w10*v10.y + w11*v11.y;
    r.z = w00*v00.z + w01*v01.z + w10*v10.z + w11*v11.z;
    r.w = w00*v00.w + w01*v01.w + w10*v10.w + w11*v11.w;
    ((float4*)(out + (((size_t)(y+1))*202 + x+1)*64))[ci4] = r;
}

// ---------------- instance norm (deterministic two-stage) ----------------
__global__ void in_rows_k(const float* __restrict__ x)   // grid 202, block 256
{
    int r = blockIdx.x;
    int c = threadIdx.x & 63;
    int q = threadIdx.x >> 6;
    const float* p = x + (size_t)r * 202 * 64;
    int pa = q * 51;
    int pb = min(pa + 51, 202);
    float s = 0.f, s2 = 0.f;
    for (int px = pa; px < pb; px++) {
        float v = p[px*64 + c];
        s += v; s2 += v*v;
    }
    g_part[(r*4 + q)*128 + c]      = s;
    g_part[(r*4 + q)*128 + 64 + c] = s2;
}

__global__ void in_stats_k()   // 1 block, 256 threads (4-way strided + tree)
{
    __shared__ float ss[4][64], sq[4][64];
    int c = threadIdx.x & 63;
    int q = threadIdx.x >> 6;
    float s = 0.f, s2 = 0.f;
    for (int r = q; r < 808; r += 4) {
        s  += g_part[r*128 + c];
        s2 += g_part[r*128 + 64 + c];
    }
    ss[q][c] = s; sq[q][c] = s2;
    __syncthreads();
    if (q == 0) {
        float S  = ss[0][c] + ss[1][c] + ss[2][c] + ss[3][c];
        float S2 = sq[0][c] + sq[1][c] + sq[2][c] + sq[3][c];
        float mu  = S * (1.f/40000.f);
        float var = S2 * (1.f/40000.f) - mu*mu;
        g_stats[c*2]   = mu;
        g_stats[c*2+1] = 1.f/sqrtf(var + 1e-5f);
    }
}

__global__ void in_apply_k(const float* __restrict__ t, const float* __restrict__ addp,
                           float* __restrict__ out)
{
    int idx = blockIdx.x * 256 + threadIdx.x;
    if (idx >= 200*200*64) return;
    int ch = idx & 63;
    int p = idx >> 6;
    int x = p % 200, y = p / 200;
    size_t o = (((size_t)(y+1))*202 + x+1)*64 + ch;
    out[o] = (t[o] - g_stats[ch*2]) * g_stats[ch*2+1] + addp[o];
}

// ---------------- launch ----------------
extern "C" void kernel_launch(void* const* d_in, const int* in_sizes, int n_in,
                              void* d_out, int out_size)
{
    const float* features = (const float*)d_in[0];
    const float* means    = (const float*)d_in[1];
    const float* cov      = (const float*)d_in[2];
    const float* opac     = (const float*)d_in[3];
    const float* emb      = (const float*)d_in[4];
    const float* conv1w   = (const float*)d_in[5];
    const float* blkw     = (const float*)d_in[6];
    const float* upw      = (const float*)d_in[7];
    float* out = (float*)d_out;

    cudaFuncSetAttribute(conv_mma_t<4,2,32,4,1>, cudaFuncAttributeMaxDynamicSharedMemorySize, SMEM100);
    cudaFuncSetAttribute(conv_mma_t<8,4,32,3,2>, cudaFuncAttributeMaxDynamicSharedMemorySize, SMEM200);

    // lazily-created side stream + fork/join events (host resources only, created once)
    static cudaStream_t sB = nullptr;
    static cudaEvent_t  eFork = nullptr, eJoin = nullptr;
    if (!sB) {
        cudaStreamCreateWithFlags(&sB, cudaStreamNonBlocking);
        cudaEventCreateWithFlags(&eFork, cudaEventDisableTiming);
        cudaEventCreateWithFlags(&eJoin, cudaEventDisableTiming);
    }

    float *s0a,*s0b,*s0c,*s0d,*b1,*b2,*b3,*b4;
    cudaGetSymbolAddress((void**)&s0a, g_s0a);
    cudaGetSymbolAddress((void**)&s0b, g_s0b);
    cudaGetSymbolAddress((void**)&s0c, g_s0c);
    cudaGetSymbolAddress((void**)&s0d, g_s0d);
    cudaGetSymbolAddress((void**)&b1,  g_b1);
    cudaGetSymbolAddress((void**)&b2,  g_b2);
    cudaGetSymbolAddress((void**)&b3,  g_b3);
    cudaGetSymbolAddress((void**)&b4,  g_b4);

    // main stream (0): prep + stage-0 path
    prep_k<<<8, 256>>>(means, cov, opac);
    prep_w<<<792, 256>>>(conv1w, blkw, upw);

    // fork: side stream does numg + render_s1 + L5 (independent of stage-0 chain)
    cudaEventRecord(eFork, 0);
    cudaStreamWaitEvent(sB, eFork, 0);

    numg_k<<<1, 256, 0, sB>>>(means, opac, out, out_size);
    render_k<<<dim3(7,7,4), 256>>>(0, features, s0a, 100);           // stream 0
    render_k<<<dim3(13,13,4), 256, 0, sB>>>(1, features, b1, 200);   // stream B

    dim3 gs0(4, 50, 2);   // 100²: co-split z=2 -> 400 CTAs
    dim3 gs1(7, 50);

    // stage 0 @100x100 (layers 0..4) — stream 0
    conv_mma_t<4,2,32,4,1><<<gs0, 128, SMEM100>>>(s0a, 0, emb, 0, s0b, 0, 0, 100, 100);
    conv_mma_t<4,2,32,4,1><<<gs0, 128, SMEM100>>>(s0b, 1, nullptr, 1, s0c, 0, 1, 100, 100);
    conv_mma_t<4,2,32,4,1><<<gs0, 128, SMEM100>>>(s0c, 2, s0b, 1, s0d, 0, 1, 100, 100);
    conv_mma_t<4,2,32,4,1><<<gs0, 128, SMEM100>>>(s0d, 3, nullptr, 1, s0b, 0, 1, 100, 100);
    conv_mma_t<4,2,32,4,1><<<gs0, 128, SMEM100>>>(s0b, 4, s0d, 1, s0c, 0, 1, 100, 100);

    // L5 on stream B (bev1 conv, needs b1 + weights only)
    conv_mma_t<8,4,32,3,2><<<gs1, 256, SMEM200, sB>>>(b1, 5, nullptr, 1, b2, 0, 0, 200, 200);
    cudaEventRecord(eJoin, sB);

    // stage-1 head on stream 0
    upsample_k<<<2500, 256>>>(s0c, b3);
    conv_mma_t<8,4,32,3,2><<<gs1, 256, SMEM200>>>(b3, 6, nullptr, 1, b4, 0, 0, 200, 200);
    in_rows_k<<<202, 256>>>(b4);
    in_stats_k<<<1, 256>>>();

    // join: in_apply needs b2 (stream B) + stats (stream 0)
    cudaStreamWaitEvent(0, eJoin, 0);
    in_apply_k<<<10000, 256>>>(b4, b2, b1);

    conv_mma_t<8,4,32,3,2><<<gs1, 256, SMEM200>>>(b1, 7, nullptr, 1, b3, 0, 1, 200, 200);
    conv_mma_t<8,4,32,3,2><<<gs1, 256, SMEM200>>>(b3, 8, b1, 1, b4, 0, 1, 200, 200);
    conv_mma_t<8,4,32,3,2><<<gs1, 256, SMEM200>>>(b4, 9, nullptr, 1, b3, 0, 1, 200, 200);
    conv_mma_t<8,4,32,3,2><<<gs1, 256, SMEM200>>>(b3, 10, b4, 1, out, 1, 1, 200, 200);
}